// round 4
// baseline (speedup 1.0000x reference)
#include <cuda_runtime.h>
#include <cuda_bf16.h>
#include <cub/cub.cuh>
#include <cstdint>

// ---------------- problem constants ----------------
#define FH_   50
#define FW_   84
#define A_    12
#define B_    4
#define PIX   (FH_*FW_)        // 4200
#define N_ANCH (PIX*A_)        // 50400
#define PRE   6000
#define POST  300
#define NW    94               // ceil(PRE/64)
#define NMS_THR 0.7f
#define NBUCK 4096
#define CAP   16384            // per-batch compacted capacity
#define INVALID_CODE 0x3FFFFFFFu
#define MROWS 256              // mask-kernel rows per CTA
#define MRT   24               // ceil(PRE/MROWS)

static_assert(NW*64 >= PRE, "NW too small");
static_assert(MRT*MROWS >= PRE, "MRT too small");

// correctly-rounded float exp: double exp rounded to float == CPU expf a.s.
__device__ __forceinline__ float exp_cr(float x) {
    return (float)exp((double)x);
}

// ---------------- static device scratch ----------------
__device__ float4       g_boxes[B_*N_ANCH];
__device__ unsigned int g_code [B_*N_ANCH];
__device__ int          g_hist [B_*NBUCK];     // memset to 0 each launch
__device__ int          g_cut  [B_];
__device__ unsigned int g_ckeys[B_*CAP];
__device__ int          g_cvals[B_*CAP];
__device__ unsigned int g_skeys[B_*CAP];
__device__ int          g_svals[B_*CAP];
__device__ float4       g_sboxes[B_*PRE];
__device__ float        g_sarea [B_*PRE];
// zero-initialized; fully-lower-triangle words are NEVER written -> stay 0
__device__ unsigned long long g_mask[(size_t)B_*PRE*NW];
__device__ unsigned char      g_temp[8u<<20];  // cub temp storage

// ---------------- kernel 1: softmax + decode + code + histogram ----------------
__global__ void prep_kernel(const float* __restrict__ scores,
                            const float* __restrict__ deltas,
                            const float* __restrict__ anchors,
                            const float* __restrict__ iminfo)
{
    int idx = blockIdx.x * blockDim.x + threadIdx.x;
    if (idx >= B_*N_ANCH) return;
    int pix = idx % PIX;
    int ba  = idx / PIX;
    int b   = ba / A_;
    int a   = ba % A_;

    const float* sp = scores + ((size_t)(b*2*A_ + 2*a))*PIX + pix;
    float s0 = sp[0];
    float s1 = sp[PIX];
    float m  = fmaxf(s0, s1);
    float e0 = exp_cr(s0 - m);
    float e1 = exp_cr(s1 - m);
    float p  = __fdiv_rn(e1, __fadd_rn(e0, e1));   // p in [0, 1]

    const float* dp = deltas + ((size_t)(b*4*A_ + 4*a))*PIX + pix;
    float d0 = dp[0], d1 = dp[PIX], d2 = dp[2*PIX], d3 = dp[3*PIX];

    int i = pix*A_ + a;
    float4 an = reinterpret_cast<const float4*>(anchors)[i];

    // exact op ordering of _bbox_transform_inv; *_rn blocks FMA contraction
    float w  = an.z - an.x + 1.0f;
    float h  = an.w - an.y + 1.0f;
    float cx = __fadd_rn(an.x, __fmul_rn(0.5f, w));
    float cy = __fadd_rn(an.y, __fmul_rn(0.5f, h));
    float pcx = __fadd_rn(__fmul_rn(d0, w), cx);
    float pcy = __fadd_rn(__fmul_rn(d1, h), cy);
    float pw  = __fmul_rn(exp_cr(d2), w);
    float ph  = __fmul_rn(exp_cr(d3), h);
    float hx  = __fmul_rn(0.5f, pw);
    float hy  = __fmul_rn(0.5f, ph);
    float x1  = __fsub_rn(pcx, hx);
    float y1  = __fsub_rn(pcy, hy);
    float x2  = __fadd_rn(pcx, hx);
    float y2  = __fadd_rn(pcy, hy);

    float imh = iminfo[b*4+0], imw = iminfo[b*4+1];
    float sh  = iminfo[b*4+2], sw  = iminfo[b*4+3];
    float mw  = imw - 1.0f, mh = imh - 1.0f;
    x1 = fminf(fmaxf(x1, 0.0f), mw);
    y1 = fminf(fmaxf(y1, 0.0f), mh);
    x2 = fminf(fmaxf(x2, 0.0f), mw);
    y2 = fminf(fmaxf(y2, 0.0f), mh);

    float ws = x2 - x1 + 1.0f;
    float hs = y2 - y1 + 1.0f;
    bool valid = (ws >= __fmul_rn(16.0f, sw)) && (hs >= __fmul_rn(16.0f, sh));

    // 30-bit descending-score code; invalid sinks to sentinel
    unsigned int code = valid ? (0x3F800000u - __float_as_uint(p)) : INVALID_CODE;

    int gi = b*N_ANCH + i;
    g_code [gi] = code;
    g_boxes[gi] = make_float4(x1, y1, x2, y2);
    atomicAdd(&g_hist[b*NBUCK + (code >> 18)], 1);
}

// ---------------- kernel 2: per-batch cutoff bucket (rank PRE) ----------------
__global__ void cutoff_kernel()
{
    int b = blockIdx.x;
    int lane = threadIdx.x;                  // 32 threads
    const unsigned FULL = 0xFFFFFFFFu;
    int running = 0;
    int cut = NBUCK - 1;
    for (int it = 0; it < NBUCK/32; it++) {
        int v = g_hist[b*NBUCK + it*32 + lane];
        int s = v;
        #pragma unroll
        for (int d = 1; d < 32; d <<= 1) {
            int t = __shfl_up_sync(FULL, s, d);
            if (lane >= d) s += t;
        }
        int cum = running + s;
        unsigned mm = __ballot_sync(FULL, cum >= PRE);
        if (mm) { cut = it*32 + __ffs(mm) - 1; break; }   // warp-uniform
        running += __shfl_sync(FULL, s, 31);
    }
    if (lane == 0) g_cut[b] = cut;
}

// ---------------- kernel 3: stable index-ordered compaction ----------------
__global__ void compact_kernel()
{
    int b   = blockIdx.x;
    int tid = threadIdx.x;                  // 1024 threads
    int wid = tid >> 5, lane = tid & 31;
    const unsigned FULL = 0xFFFFFFFFu;

    __shared__ int warpOff[32];
    __shared__ int sBase, sRunning;

    // fill padded region with sentinel keys
    unsigned int fillKey = ((unsigned int)b << 30) | INVALID_CODE;
    for (int j = tid; j < CAP; j += 1024) {
        g_ckeys[b*CAP + j] = fillKey;
        g_cvals[b*CAP + j] = 0;
    }
    if (tid == 0) sRunning = 0;
    __syncthreads();

    int cut = g_cut[b];
    for (int base = 0; base < N_ANCH; base += 1024) {
        int i = base + tid;
        unsigned int code = (i < N_ANCH) ? g_code[b*N_ANCH + i] : INVALID_CODE;
        bool pred = (i < N_ANCH) && ((int)(code >> 18) <= cut);
        unsigned mm = __ballot_sync(FULL, pred);
        int prefix = __popc(mm & ((1u << lane) - 1u));
        if (lane == 0) warpOff[wid] = __popc(mm);
        __syncthreads();
        if (tid == 0) {
            int ex = 0;
            #pragma unroll
            for (int wv = 0; wv < 32; wv++) { int t = warpOff[wv]; warpOff[wv] = ex; ex += t; }
            sBase = sRunning;
            sRunning = sRunning + ex;
        }
        __syncthreads();
        if (pred) {
            int pos = sBase + warpOff[wid] + prefix;
            if (pos < CAP) {
                g_ckeys[b*CAP + pos] = ((unsigned int)b << 30) | code;
                g_cvals[b*CAP + pos] = b*N_ANCH + i;
            }
        }
        __syncthreads();
    }
}

// ---------------- kernel 4: gather top-PRE boxes per batch + areas ----------------
__global__ void gather_kernel()
{
    int t = blockIdx.x * blockDim.x + threadIdx.x;
    if (t >= B_*PRE) return;
    int b = t / PRE;
    int r = t % PRE;
    int v = g_svals[b*CAP + r];
    float4 bx = g_boxes[v];
    g_sboxes[t] = bx;
    g_sarea[t]  = (bx.z - bx.x + 1.0f) * (bx.w - bx.y + 1.0f);
}

// ---------------- kernel 5: IoU suppression bitmask, 256x64 tiles ----------------
__global__ void nms_mask_kernel()
{
    int cb = blockIdx.x;                    // column 64-block
    int rt = blockIdx.y;                    // row 256-tile
    int b  = blockIdx.z;
    int j0 = cb * 64;
    if (j0 + 63 < rt * MROWS) return;       // tile fully below diagonal: stays 0

    __shared__ float4 cbox[64];
    __shared__ float  carea[64];
    int t = threadIdx.x;                    // 256 threads
    if (t < 64) {
        int jj = j0 + t;
        if (jj < PRE) { cbox[t] = g_sboxes[b*PRE + jj]; carea[t] = g_sarea[b*PRE + jj]; }
    }
    __syncthreads();

    int i = rt * MROWS + t;
    if (i >= PRE) return;
    int d = i - j0;                          // clear bits k <= d
    size_t word = ((size_t)(b*PRE + i))*NW + cb;
    if (d >= 63) { g_mask[word] = 0ull; return; }

    float4 bi = g_sboxes[b*PRE + i];
    float  ai = g_sarea [b*PRE + i];

    unsigned long long bits = 0ull;
    int jmax = min(64, PRE - j0);
    #pragma unroll 8
    for (int k = 0; k < jmax; k++) {
        float4 bj = cbox[k];
        float xx1 = fmaxf(bi.x, bj.x);
        float yy1 = fmaxf(bi.y, bj.y);
        float xx2 = fminf(bi.z, bj.z);
        float yy2 = fminf(bi.w, bj.w);
        float iw = fmaxf(xx2 - xx1 + 1.0f, 0.0f);
        float ih = fmaxf(yy2 - yy1 + 1.0f, 0.0f);
        float inter = __fmul_rn(iw, ih);
        float sum   = __fadd_rn(ai, carea[k]);
        // exact prefilter: iou>0.7 needs inter>0.41*sum; 4*inter>=sum is a
        // safe necessary condition (slack 1.6x >> rounding) -> identical bits
        if (__fmul_rn(inter, 4.0f) >= sum) {
            float uni = __fsub_rn(sum, inter);
            float iou = __fdiv_rn(inter, uni);
            if (iou > NMS_THR) bits |= (1ull << k);
        }
    }
    if (d >= 0) bits &= (~0ull) << (d + 1);
    g_mask[word] = bits;
}

// ---------------- kernel 6: warp-serial greedy scan + output write ----------------
__global__ void nms_scan_kernel(float* __restrict__ out)
{
    int b    = blockIdx.x;
    int lane = threadIdx.x;        // 32 threads
    const unsigned FULL = 0xFFFFFFFFu;

    __shared__ unsigned long long removed[NW];
    __shared__ int keptList[POST];
    for (int w = lane; w < NW; w += 32) removed[w] = 0ull;
    __syncwarp();

    int kept = 0;
    for (int c = 0; c < NW && kept < POST; c++) {
        int r0 = c * 64;
        int ra = r0 + lane, rb2 = r0 + 32 + lane;

        bool va = (ra  < PRE) && ((g_skeys[b*CAP + ra ] & 0x3FFFFFFFu) != INVALID_CODE);
        bool vb = (rb2 < PRE) && ((g_skeys[b*CAP + rb2] & 0x3FFFFFFFu) != INVALID_CODE);
        unsigned lo = __ballot_sync(FULL, va);
        unsigned hi = __ballot_sync(FULL, vb);
        unsigned long long validm = (unsigned long long)lo | ((unsigned long long)hi << 32);

        unsigned long long m0 = (ra  < PRE) ? g_mask[((size_t)(b*PRE + ra ))*NW + c] : 0ull;
        unsigned long long m1 = (rb2 < PRE) ? g_mask[((size_t)(b*PRE + rb2))*NW + c] : 0ull;

        unsigned long long cand = validm & ~removed[c];
        unsigned long long keptbits = 0ull;
        while (cand && kept < POST) {                 // warp-uniform
            int l = __ffsll((long long)cand) - 1;
            keptList[kept] = r0 + l;
            kept++;
            keptbits |= (1ull << l);
            unsigned long long intra = (l < 32) ? __shfl_sync(FULL, m0, l)
                                                : __shfl_sync(FULL, m1, l - 32);
            cand &= ~intra;
            cand &= ~(1ull << l);
        }

        if (keptbits) {
            unsigned long long acc0 = 0, acc1 = 0, acc2 = 0;
            int w0 = lane, w1 = lane + 32, w2 = lane + 64;
            unsigned long long kb2 = keptbits;
            while (kb2) {
                int l = __ffsll((long long)kb2) - 1;
                kb2 &= kb2 - 1;
                const unsigned long long* row = &g_mask[((size_t)(b*PRE + r0 + l))*NW];
                acc0 |= row[w0];
                if (w1 < NW) acc1 |= row[w1];
                if (w2 < NW) acc2 |= row[w2];
            }
            removed[w0] |= acc0;
            if (w1 < NW) removed[w1] |= acc1;
            if (w2 < NW) removed[w2] |= acc2;
        }
        __syncwarp();
    }

    for (int r = lane; r < POST; r += 32) {
        float* o = out + ((size_t)(b*POST + r))*5;
        if (r < kept) {
            float4 bx = g_sboxes[b*PRE + keptList[r]];
            o[0] = (float)b; o[1] = bx.x; o[2] = bx.y; o[3] = bx.z; o[4] = bx.w;
        } else {
            o[0] = (float)b; o[1] = 0.0f; o[2] = 0.0f; o[3] = 0.0f; o[4] = 0.0f;
        }
    }
}

// ---------------- launch ----------------
extern "C" void kernel_launch(void* const* d_in, const int* in_sizes, int n_in,
                              void* d_out, int out_size)
{
    const float* scores  = (const float*)d_in[0];
    const float* deltas  = (const float*)d_in[1];
    const float* anchors = (const float*)d_in[2];
    const float* iminfo  = (const float*)d_in[3];
    float* out = (float*)d_out;

    void *hist, *ckeys, *skeys, *cvals, *svals, *temp;
    cudaGetSymbolAddress(&hist,  g_hist);
    cudaGetSymbolAddress(&ckeys, g_ckeys);
    cudaGetSymbolAddress(&skeys, g_skeys);
    cudaGetSymbolAddress(&cvals, g_cvals);
    cudaGetSymbolAddress(&svals, g_svals);
    cudaGetSymbolAddress(&temp,  g_temp);

    cudaMemsetAsync(hist, 0, B_*NBUCK*sizeof(int), 0);

    const int total = B_ * N_ANCH;
    prep_kernel<<<(total + 255) / 256, 256>>>(scores, deltas, anchors, iminfo);

    cutoff_kernel<<<B_, 32>>>();
    compact_kernel<<<B_, 1024>>>();

    // stable radix sort of the compacted+padded 32-bit composite keys
    size_t temp_bytes = 0;
    cub::DeviceRadixSort::SortPairs(nullptr, temp_bytes,
        (const unsigned int*)ckeys, (unsigned int*)skeys,
        (const int*)cvals, (int*)svals, B_*CAP, 0, 32);
    if (temp_bytes <= sizeof(g_temp)) {
        cub::DeviceRadixSort::SortPairs(temp, temp_bytes,
            (const unsigned int*)ckeys, (unsigned int*)skeys,
            (const int*)cvals, (int*)svals, B_*CAP, 0, 32, (cudaStream_t)0);
    }

    gather_kernel<<<(B_*PRE + 255) / 256, 256>>>();

    dim3 mgrid(NW, MRT, B_);
    nms_mask_kernel<<<mgrid, MROWS>>>();

    nms_scan_kernel<<<B_, 32>>>(out);
}

// round 5
// speedup vs baseline: 1.1735x; 1.1735x over previous
#include <cuda_runtime.h>
#include <cuda_bf16.h>
#include <cub/cub.cuh>
#include <cstdint>

// ---------------- problem constants ----------------
#define FH_   50
#define FW_   84
#define A_    12
#define B_    4
#define PIX   (FH_*FW_)        // 4200
#define N_ANCH (PIX*A_)        // 50400
#define PRE   6000
#define POST  300
#define NW    94               // ceil(PRE/64)
#define NMS_THR 0.7f
#define MROWS 256              // mask-kernel rows per CTA
#define MRT   24               // ceil(PRE/MROWS)

static_assert(NW*64 >= PRE, "NW too small");
static_assert(MRT*MROWS >= PRE, "MRT too small");

// Correctly-rounded float exp, fast path: short fp64 reduction+poly (rel err
// < 2^-45), Ziv check, rare fallback to libdevice exp. Returns a value
// bit-identical to (float)exp((double)x) for every input.
__device__ __forceinline__ float exp_cr(float x) {
    double xd = (double)x;
    double t  = xd * 1.4426950408889634;              // x/ln2
    int    k  = __double2int_rn(t);
    double kd = (double)k;
    double r  = __fma_rn(kd, -0.6931471805599453,    xd);   // ln2_hi
    r         = __fma_rn(kd, -2.3190468138462996e-17, r);   // ln2_lo
    // e^r, |r| <= 0.3466: degree-11 Taylor, Horner (11 DFMA)
    double p = 2.505210838544172e-08;                 // 1/11!
    p = __fma_rn(p, r, 2.755731922398589e-07);        // 1/10!
    p = __fma_rn(p, r, 2.7557319223985893e-06);       // 1/9!
    p = __fma_rn(p, r, 2.48015873015873e-05);         // 1/8!
    p = __fma_rn(p, r, 1.984126984126984e-04);        // 1/7!
    p = __fma_rn(p, r, 1.3888888888888889e-03);       // 1/6!
    p = __fma_rn(p, r, 8.333333333333333e-03);        // 1/5!
    p = __fma_rn(p, r, 4.1666666666666664e-02);       // 1/4!
    p = __fma_rn(p, r, 0.16666666666666666);          // 1/3!
    p = __fma_rn(p, r, 0.5);
    p = __fma_rn(p, r, 1.0);
    p = __fma_rn(p, r, 1.0);
    double yd = p * __longlong_as_double((long long)(1023 + k) << 52);  // * 2^k
    // Ziv rounding test: if the +-1e-12 rel interval rounds to one float,
    // that float is the correct rounding of the true exp(x).
    float flo = (float)(yd * (1.0 - 1.0e-12));
    float fhi = (float)(yd * (1.0 + 1.0e-12));
    if (flo == fhi) return flo;
    return (float)exp(xd);                            // rare (~2^-15) fallback
}

// ---------------- static device scratch (no allocations allowed) ----------------
__device__ unsigned int       g_keys    [B_*N_ANCH];
__device__ unsigned int       g_keys_out[B_*N_ANCH];
__device__ int                g_vals    [B_*N_ANCH];
__device__ int                g_vals_out[B_*N_ANCH];
__device__ float4             g_boxes   [B_*N_ANCH];
__device__ float4             g_sboxes  [B_*PRE];
__device__ float              g_sarea   [B_*PRE];
// zero-initialized; fully-lower-triangle words are NEVER written -> stay 0
__device__ unsigned long long g_mask[(size_t)B_*PRE*NW];
__device__ unsigned char      g_temp[32u<<20];   // cub temp storage

// ---------------- kernel 1: score softmax + bbox decode ----------------
__global__ void prep_kernel(const float* __restrict__ scores,
                            const float* __restrict__ deltas,
                            const float* __restrict__ anchors,
                            const float* __restrict__ iminfo)
{
    int idx = blockIdx.x * blockDim.x + threadIdx.x;
    if (idx >= B_*N_ANCH) return;
    int pix = idx % PIX;
    int ba  = idx / PIX;
    int b   = ba / A_;
    int a   = ba % A_;

    // softmax over (2a, 2a+1): m = max -> one exp is exactly 1.0, so a single
    // E = exp(-|s1-s0|) reproduces the reference bitwise:
    //   s0 >  s1: p = fl(E / fl(1+E))
    //   s1 >= s0: p = fl(1 / fl(E+1))
    const float* sp = scores + ((size_t)(b*2*A_ + 2*a))*PIX + pix;
    float s0 = sp[0];
    float s1 = sp[PIX];
    float dneg = (s1 >= s0) ? __fsub_rn(s0, s1) : __fsub_rn(s1, s0);
    float E     = exp_cr(dneg);
    float denom = __fadd_rn(E, 1.0f);                 // == fl(1+E) bitwise
    float p = (s1 >= s0) ? __fdiv_rn(1.0f, denom) : __fdiv_rn(E, denom);

    const float* dp = deltas + ((size_t)(b*4*A_ + 4*a))*PIX + pix;
    float d0 = dp[0], d1 = dp[PIX], d2 = dp[2*PIX], d3 = dp[3*PIX];

    int i = pix*A_ + a;
    float4 an = reinterpret_cast<const float4*>(anchors)[i];

    // exact op ordering of _bbox_transform_inv; *_rn blocks FMA contraction
    float w  = an.z - an.x + 1.0f;
    float h  = an.w - an.y + 1.0f;
    float cx = __fadd_rn(an.x, __fmul_rn(0.5f, w));
    float cy = __fadd_rn(an.y, __fmul_rn(0.5f, h));
    float pcx = __fadd_rn(__fmul_rn(d0, w), cx);
    float pcy = __fadd_rn(__fmul_rn(d1, h), cy);
    float pw  = __fmul_rn(exp_cr(d2), w);
    float ph  = __fmul_rn(exp_cr(d3), h);
    float hx  = __fmul_rn(0.5f, pw);
    float hy  = __fmul_rn(0.5f, ph);
    float x1  = __fsub_rn(pcx, hx);
    float y1  = __fsub_rn(pcy, hy);
    float x2  = __fadd_rn(pcx, hx);
    float y2  = __fadd_rn(pcy, hy);

    float imh = iminfo[b*4+0], imw = iminfo[b*4+1];
    float sh  = iminfo[b*4+2], sw  = iminfo[b*4+3];
    float mw  = imw - 1.0f, mh = imh - 1.0f;
    x1 = fminf(fmaxf(x1, 0.0f), mw);
    y1 = fminf(fmaxf(y1, 0.0f), mh);
    x2 = fminf(fmaxf(x2, 0.0f), mw);
    y2 = fminf(fmaxf(y2, 0.0f), mh);

    float ws = x2 - x1 + 1.0f;
    float hs = y2 - y1 + 1.0f;
    bool valid = (ws >= __fmul_rn(16.0f, sw)) && (hs >= __fmul_rn(16.0f, sh));

    // 32-bit composite key: bits[30,32)=batch, bits[0,30)=descending-score code
    unsigned int desc = valid ? (0x3F800000u - __float_as_uint(p)) : 0x3FFFFFFFu;
    unsigned int key  = ((unsigned int)b << 30) | desc;

    int gi = b*N_ANCH + i;
    g_keys[gi]  = key;
    g_vals[gi]  = gi;
    g_boxes[gi] = make_float4(x1, y1, x2, y2);
}

// ---------------- kernel 2: gather top-PRE boxes per batch + areas ----------------
__global__ void gather_kernel()
{
    int t = blockIdx.x * blockDim.x + threadIdx.x;
    if (t >= B_*PRE) return;
    int b = t / PRE;
    int r = t % PRE;
    int v = g_vals_out[b*N_ANCH + r];
    float4 bx = g_boxes[v];
    g_sboxes[t] = bx;
    g_sarea[t]  = (bx.z - bx.x + 1.0f) * (bx.w - bx.y + 1.0f);
}

// ---------------- kernel 3: IoU suppression bitmask, 256x64 tiles ----------------
__global__ void nms_mask_kernel()
{
    int cb = blockIdx.x;                    // column 64-block
    int rt = blockIdx.y;                    // row 256-tile
    int b  = blockIdx.z;
    int j0 = cb * 64;
    if (j0 + 63 < rt * MROWS) return;       // tile fully below diagonal: stays 0

    __shared__ float4 cbox[64];
    __shared__ float  carea[64];
    int t = threadIdx.x;                    // 256 threads
    if (t < 64) {
        int jj = j0 + t;
        if (jj < PRE) { cbox[t] = g_sboxes[b*PRE + jj]; carea[t] = g_sarea[b*PRE + jj]; }
    }
    __syncthreads();

    int i = rt * MROWS + t;
    if (i >= PRE) return;
    int d = i - j0;                          // bits k <= d must be cleared
    size_t word = ((size_t)(b*PRE + i))*NW + cb;
    if (d >= 63) { g_mask[word] = 0ull; return; }

    float4 bi = g_sboxes[b*PRE + i];
    float  ai = g_sarea [b*PRE + i];

    unsigned long long bits = 0ull;
    int jmax = min(64, PRE - j0);
    #pragma unroll 8
    for (int k = 0; k < jmax; k++) {
        float4 bj = cbox[k];
        float xx1 = fmaxf(bi.x, bj.x);
        float yy1 = fmaxf(bi.y, bj.y);
        float xx2 = fminf(bi.z, bj.z);
        float yy2 = fminf(bi.w, bj.w);
        float iw = fmaxf(xx2 - xx1 + 1.0f, 0.0f);
        float ih = fmaxf(yy2 - yy1 + 1.0f, 0.0f);
        float inter = __fmul_rn(iw, ih);
        float sum   = __fadd_rn(ai, carea[k]);
        // exact prefilter: iou>0.7 needs inter>0.41*sum; 4*inter>=sum is a
        // safe necessary condition (slack 1.6x >> rounding) -> identical bits
        if (__fmul_rn(inter, 4.0f) >= sum) {
            float uni = __fsub_rn(sum, inter);
            float iou = __fdiv_rn(inter, uni);
            if (iou > NMS_THR) bits |= (1ull << k);
        }
    }
    if (d >= 0) bits &= (~0ull) << (d + 1);
    g_mask[word] = bits;
}

// ---------------- kernel 4: warp-serial greedy scan + output write ----------------
__global__ void nms_scan_kernel(float* __restrict__ out)
{
    int b    = blockIdx.x;
    int lane = threadIdx.x;        // 32 threads
    const unsigned FULL = 0xFFFFFFFFu;

    __shared__ unsigned long long removed[NW];
    __shared__ int keptList[POST];
    for (int w = lane; w < NW; w += 32) removed[w] = 0ull;
    __syncwarp();

    int kept = 0;
    for (int c = 0; c < NW && kept < POST; c++) {
        int r0 = c * 64;
        int ra = r0 + lane, rb2 = r0 + 32 + lane;

        bool va = (ra  < PRE) && ((g_keys_out[b*N_ANCH + ra ] & 0x3FFFFFFFu) != 0x3FFFFFFFu);
        bool vb = (rb2 < PRE) && ((g_keys_out[b*N_ANCH + rb2] & 0x3FFFFFFFu) != 0x3FFFFFFFu);
        unsigned lo = __ballot_sync(FULL, va);
        unsigned hi = __ballot_sync(FULL, vb);
        unsigned long long validm = (unsigned long long)lo | ((unsigned long long)hi << 32);

        unsigned long long m0 = (ra  < PRE) ? g_mask[((size_t)(b*PRE + ra ))*NW + c] : 0ull;
        unsigned long long m1 = (rb2 < PRE) ? g_mask[((size_t)(b*PRE + rb2))*NW + c] : 0ull;

        unsigned long long cand = validm & ~removed[c];
        unsigned long long keptbits = 0ull;
        while (cand && kept < POST) {                 // warp-uniform
            int l = __ffsll((long long)cand) - 1;
            keptList[kept] = r0 + l;
            kept++;
            keptbits |= (1ull << l);
            unsigned long long intra = (l < 32) ? __shfl_sync(FULL, m0, l)
                                                : __shfl_sync(FULL, m1, l - 32);
            cand &= ~intra;
            cand &= ~(1ull << l);
        }

        if (keptbits) {
            unsigned long long acc0 = 0, acc1 = 0, acc2 = 0;
            int w0 = lane, w1 = lane + 32, w2 = lane + 64;
            unsigned long long kb2 = keptbits;
            while (kb2) {
                int l = __ffsll((long long)kb2) - 1;
                kb2 &= kb2 - 1;
                const unsigned long long* row = &g_mask[((size_t)(b*PRE + r0 + l))*NW];
                acc0 |= row[w0];
                if (w1 < NW) acc1 |= row[w1];
                if (w2 < NW) acc2 |= row[w2];
            }
            removed[w0] |= acc0;
            if (w1 < NW) removed[w1] |= acc1;
            if (w2 < NW) removed[w2] |= acc2;
        }
        __syncwarp();
    }

    for (int r = lane; r < POST; r += 32) {
        float* o = out + ((size_t)(b*POST + r))*5;
        if (r < kept) {
            float4 bx = g_sboxes[b*PRE + keptList[r]];
            o[0] = (float)b; o[1] = bx.x; o[2] = bx.y; o[3] = bx.z; o[4] = bx.w;
        } else {
            o[0] = (float)b; o[1] = 0.0f; o[2] = 0.0f; o[3] = 0.0f; o[4] = 0.0f;
        }
    }
}

// ---------------- launch ----------------
extern "C" void kernel_launch(void* const* d_in, const int* in_sizes, int n_in,
                              void* d_out, int out_size)
{
    const float* scores  = (const float*)d_in[0];
    const float* deltas  = (const float*)d_in[1];
    const float* anchors = (const float*)d_in[2];
    const float* iminfo  = (const float*)d_in[3];
    float* out = (float*)d_out;

    void *keys, *keysOut, *vals, *valsOut, *temp;
    cudaGetSymbolAddress(&keys,    g_keys);
    cudaGetSymbolAddress(&keysOut, g_keys_out);
    cudaGetSymbolAddress(&vals,    g_vals);
    cudaGetSymbolAddress(&valsOut, g_vals_out);
    cudaGetSymbolAddress(&temp,    g_temp);

    const int total = B_ * N_ANCH;
    prep_kernel<<<(total + 255) / 256, 256>>>(scores, deltas, anchors, iminfo);

    // one stable ascending radix sort over 32-bit composite keys (4 passes)
    size_t temp_bytes = 0;
    cub::DeviceRadixSort::SortPairs(nullptr, temp_bytes,
        (const unsigned int*)keys, (unsigned int*)keysOut,
        (const int*)vals, (int*)valsOut, total, 0, 32);
    if (temp_bytes <= sizeof(g_temp)) {
        cub::DeviceRadixSort::SortPairs(temp, temp_bytes,
            (const unsigned int*)keys, (unsigned int*)keysOut,
            (const int*)vals, (int*)valsOut, total, 0, 32, (cudaStream_t)0);
    }

    gather_kernel<<<(B_*PRE + 255) / 256, 256>>>();

    dim3 mgrid(NW, MRT, B_);
    nms_mask_kernel<<<mgrid, MROWS>>>();

    nms_scan_kernel<<<B_, 32>>>(out);
}

// round 6
// speedup vs baseline: 1.8280x; 1.5577x over previous
#include <cuda_runtime.h>
#include <cuda_bf16.h>
#include <cub/cub.cuh>
#include <cstdint>

// ---------------- problem constants ----------------
#define FH_   50
#define FW_   84
#define A_    12
#define B_    4
#define PIX   (FH_*FW_)        // 4200
#define N_ANCH (PIX*A_)        // 50400
#define PRE   6000
#define POST  300
#define NW    94               // ceil(PRE/64)
#define NMS_THR 0.7f
#define MROWS 256              // mask-kernel rows per CTA
#define MRT   24               // ceil(PRE/MROWS)
// phase-1 (lazy) corner: top R1 rows x R1 cols
#define R1    2048
#define CH1   32               // R1/64 column words
#define RT1   8                // R1/MROWS row tiles

static_assert(NW*64 >= PRE, "NW too small");
static_assert(MRT*MROWS >= PRE, "MRT too small");
static_assert(CH1*64 == R1 && RT1*MROWS == R1, "phase1 dims");

// Correctly-rounded float exp: short fp64 poly + Ziv check, rare libdevice
// fallback. Bit-identical to (float)exp((double)x) for every input.
__device__ __forceinline__ float exp_cr(float x) {
    double xd = (double)x;
    double t  = xd * 1.4426950408889634;              // x/ln2
    int    k  = __double2int_rn(t);
    double kd = (double)k;
    double r  = __fma_rn(kd, -0.6931471805599453,    xd);   // ln2_hi
    r         = __fma_rn(kd, -2.3190468138462996e-17, r);   // ln2_lo
    double p = 2.505210838544172e-08;                 // 1/11!
    p = __fma_rn(p, r, 2.755731922398589e-07);
    p = __fma_rn(p, r, 2.7557319223985893e-06);
    p = __fma_rn(p, r, 2.48015873015873e-05);
    p = __fma_rn(p, r, 1.984126984126984e-04);
    p = __fma_rn(p, r, 1.3888888888888889e-03);
    p = __fma_rn(p, r, 8.333333333333333e-03);
    p = __fma_rn(p, r, 4.1666666666666664e-02);
    p = __fma_rn(p, r, 0.16666666666666666);
    p = __fma_rn(p, r, 0.5);
    p = __fma_rn(p, r, 1.0);
    p = __fma_rn(p, r, 1.0);
    double yd = p * __longlong_as_double((long long)(1023 + k) << 52);
    float flo = (float)(yd * (1.0 - 1.0e-12));
    float fhi = (float)(yd * (1.0 + 1.0e-12));
    if (flo == fhi) return flo;
    return (float)exp(xd);                            // ~2^-15 fallback
}

// ---------------- static device scratch ----------------
__device__ unsigned int       g_keys    [B_*N_ANCH];
__device__ unsigned int       g_keys_out[B_*N_ANCH];
__device__ int                g_vals    [B_*N_ANCH];
__device__ int                g_vals_out[B_*N_ANCH];
__device__ float4             g_boxes   [B_*N_ANCH];
__device__ float4             g_sboxes  [B_*PRE];
__device__ float              g_sarea   [B_*PRE];
__device__ int                g_done    [B_];
// phase-1 corner mask (zero-init; lower-tri words never written -> stay 0)
__device__ unsigned long long g_mask1[(size_t)B_*R1*CH1];
// full mask, fallback only (zero-init; lower-tri words never written)
__device__ unsigned long long g_mask[(size_t)B_*PRE*NW];
__device__ unsigned char      g_temp[32u<<20];   // cub temp storage

// ---------------- kernel 1: score softmax + bbox decode ----------------
__global__ void prep_kernel(const float* __restrict__ scores,
                            const float* __restrict__ deltas,
                            const float* __restrict__ anchors,
                            const float* __restrict__ iminfo)
{
    int idx = blockIdx.x * blockDim.x + threadIdx.x;
    if (idx >= B_*N_ANCH) return;
    int pix = idx % PIX;
    int ba  = idx / PIX;
    int b   = ba / A_;
    int a   = ba % A_;

    // softmax over (2a,2a+1): max-shift makes one exp exactly 1.0, so a
    // single E=exp(-|s1-s0|) reproduces the reference bitwise.
    const float* sp = scores + ((size_t)(b*2*A_ + 2*a))*PIX + pix;
    float s0 = sp[0];
    float s1 = sp[PIX];
    float dneg = (s1 >= s0) ? __fsub_rn(s0, s1) : __fsub_rn(s1, s0);
    float E     = exp_cr(dneg);
    float denom = __fadd_rn(E, 1.0f);
    float p = (s1 >= s0) ? __fdiv_rn(1.0f, denom) : __fdiv_rn(E, denom);

    const float* dp = deltas + ((size_t)(b*4*A_ + 4*a))*PIX + pix;
    float d0 = dp[0], d1 = dp[PIX], d2 = dp[2*PIX], d3 = dp[3*PIX];

    int i = pix*A_ + a;
    float4 an = reinterpret_cast<const float4*>(anchors)[i];

    float w  = an.z - an.x + 1.0f;
    float h  = an.w - an.y + 1.0f;
    float cx = __fadd_rn(an.x, __fmul_rn(0.5f, w));
    float cy = __fadd_rn(an.y, __fmul_rn(0.5f, h));
    float pcx = __fadd_rn(__fmul_rn(d0, w), cx);
    float pcy = __fadd_rn(__fmul_rn(d1, h), cy);
    float pw  = __fmul_rn(exp_cr(d2), w);
    float ph  = __fmul_rn(exp_cr(d3), h);
    float hx  = __fmul_rn(0.5f, pw);
    float hy  = __fmul_rn(0.5f, ph);
    float x1  = __fsub_rn(pcx, hx);
    float y1  = __fsub_rn(pcy, hy);
    float x2  = __fadd_rn(pcx, hx);
    float y2  = __fadd_rn(pcy, hy);

    float imh = iminfo[b*4+0], imw = iminfo[b*4+1];
    float sh  = iminfo[b*4+2], sw  = iminfo[b*4+3];
    float mw  = imw - 1.0f, mh = imh - 1.0f;
    x1 = fminf(fmaxf(x1, 0.0f), mw);
    y1 = fminf(fmaxf(y1, 0.0f), mh);
    x2 = fminf(fmaxf(x2, 0.0f), mw);
    y2 = fminf(fmaxf(y2, 0.0f), mh);

    float ws = x2 - x1 + 1.0f;
    float hs = y2 - y1 + 1.0f;
    bool valid = (ws >= __fmul_rn(16.0f, sw)) && (hs >= __fmul_rn(16.0f, sh));

    unsigned int desc = valid ? (0x3F800000u - __float_as_uint(p)) : 0x3FFFFFFFu;
    unsigned int key  = ((unsigned int)b << 30) | desc;

    int gi = b*N_ANCH + i;
    g_keys[gi]  = key;
    g_vals[gi]  = gi;
    g_boxes[gi] = make_float4(x1, y1, x2, y2);
}

// ---------------- kernel 2: gather top-PRE boxes per batch + areas ----------------
__global__ void gather_kernel()
{
    int t = blockIdx.x * blockDim.x + threadIdx.x;
    if (t >= B_*PRE) return;
    int b = t / PRE;
    int r = t % PRE;
    int v = g_vals_out[b*N_ANCH + r];
    float4 bx = g_boxes[v];
    g_sboxes[t] = bx;
    g_sarea[t]  = (bx.z - bx.x + 1.0f) * (bx.w - bx.y + 1.0f);
}

// ---------------- shared IoU bit computation ----------------
__device__ __forceinline__ unsigned long long iou_bits(
    float4 bi, float ai, const float4* cbox, const float* carea, int jmax)
{
    unsigned long long bits = 0ull;
    #pragma unroll 8
    for (int k = 0; k < jmax; k++) {
        float4 bj = cbox[k];
        float xx1 = fmaxf(bi.x, bj.x);
        float yy1 = fmaxf(bi.y, bj.y);
        float xx2 = fminf(bi.z, bj.z);
        float yy2 = fminf(bi.w, bj.w);
        float iw = fmaxf(xx2 - xx1 + 1.0f, 0.0f);
        float ih = fmaxf(yy2 - yy1 + 1.0f, 0.0f);
        float inter = __fmul_rn(iw, ih);
        float sum   = __fadd_rn(ai, carea[k]);
        // exact prefilter: iou>0.7 requires inter>0.41*sum; 4*inter>=sum is a
        // safe necessary condition -> kept-bit set is bit-identical
        if (__fmul_rn(inter, 4.0f) >= sum) {
            float uni = __fsub_rn(sum, inter);
            float iou = __fdiv_rn(inter, uni);
            if (iou > NMS_THR) bits |= (1ull << k);
        }
    }
    return bits;
}

// ---------------- kernel 3a: phase-1 corner mask (top R1 x R1) ----------------
__global__ void mask1_kernel()
{
    int cb = blockIdx.x;                    // column word, < CH1
    int rt = blockIdx.y;                    // row 256-tile, < RT1
    int b  = blockIdx.z;
    int j0 = cb * 64;
    if (j0 + 63 < rt * MROWS) return;       // fully-lower tile: words stay 0

    __shared__ float4 cbox[64];
    __shared__ float  carea[64];
    int t = threadIdx.x;
    if (t < 64) {
        cbox[t]  = g_sboxes[b*PRE + j0 + t];
        carea[t] = g_sarea [b*PRE + j0 + t];
    }
    __syncthreads();

    int i = rt * MROWS + t;                 // < R1 <= PRE
    int d = i - j0;
    size_t word = ((size_t)(b*R1 + i))*CH1 + cb;
    if (d >= 63) { g_mask1[word] = 0ull; return; }

    float4 bi = g_sboxes[b*PRE + i];
    float  ai = g_sarea [b*PRE + i];
    unsigned long long bits = iou_bits(bi, ai, cbox, carea, 64);
    if (d >= 0) bits &= (~0ull) << (d + 1);
    g_mask1[word] = bits;
}

// ---------------- kernel 3b: phase-1 scan over corner; sets g_done ----------------
__global__ void scan1_kernel(float* __restrict__ out)
{
    int b    = blockIdx.x;
    int lane = threadIdx.x;        // 32 threads
    const unsigned FULL = 0xFFFFFFFFu;

    __shared__ unsigned long long removed[CH1];
    __shared__ int keptList[POST];
    if (lane < CH1) removed[lane] = 0ull;
    __syncwarp();

    int kept = 0;
    for (int c = 0; c < CH1 && kept < POST; c++) {
        int r0 = c * 64;
        int ra = r0 + lane, rb2 = r0 + 32 + lane;   // both < R1

        bool va = (g_keys_out[b*N_ANCH + ra ] & 0x3FFFFFFFu) != 0x3FFFFFFFu;
        bool vb = (g_keys_out[b*N_ANCH + rb2] & 0x3FFFFFFFu) != 0x3FFFFFFFu;
        unsigned lo = __ballot_sync(FULL, va);
        unsigned hi = __ballot_sync(FULL, vb);
        unsigned long long validm = (unsigned long long)lo | ((unsigned long long)hi << 32);

        unsigned long long m0 = g_mask1[((size_t)(b*R1 + ra ))*CH1 + c];
        unsigned long long m1 = g_mask1[((size_t)(b*R1 + rb2))*CH1 + c];

        unsigned long long cand = validm & ~removed[c];
        unsigned long long keptbits = 0ull;
        while (cand && kept < POST) {
            int l = __ffsll((long long)cand) - 1;
            keptList[kept] = r0 + l;
            kept++;
            keptbits |= (1ull << l);
            unsigned long long intra = (l < 32) ? __shfl_sync(FULL, m0, l)
                                                : __shfl_sync(FULL, m1, l - 32);
            cand &= ~intra;
            cand &= ~(1ull << l);
        }

        if (keptbits) {
            unsigned long long acc = 0ull;           // lane -> word, CH1==32
            unsigned long long kb2 = keptbits;
            while (kb2) {
                int l = __ffsll((long long)kb2) - 1;
                kb2 &= kb2 - 1;
                acc |= g_mask1[((size_t)(b*R1 + r0 + l))*CH1 + lane];
            }
            removed[lane] |= acc;
        }
        __syncwarp();
    }

    if (kept >= POST) {
        if (lane == 0) g_done[b] = 1;
        for (int r = lane; r < POST; r += 32) {
            float* o = out + ((size_t)(b*POST + r))*5;
            float4 bx = g_sboxes[b*PRE + keptList[r]];
            o[0] = (float)b; o[1] = bx.x; o[2] = bx.y; o[3] = bx.z; o[4] = bx.w;
        }
    } else {
        if (lane == 0) g_done[b] = 0;   // phase 2 handles this batch
    }
}

// ---------------- kernel 4a: full mask (fallback, per-batch early exit) ----------------
__global__ void nms_mask_kernel()
{
    int b  = blockIdx.z;
    if (g_done[b]) return;
    int cb = blockIdx.x;
    int rt = blockIdx.y;
    int j0 = cb * 64;
    if (j0 + 63 < rt * MROWS) return;

    __shared__ float4 cbox[64];
    __shared__ float  carea[64];
    int t = threadIdx.x;
    if (t < 64) {
        int jj = j0 + t;
        if (jj < PRE) { cbox[t] = g_sboxes[b*PRE + jj]; carea[t] = g_sarea[b*PRE + jj]; }
    }
    __syncthreads();

    int i = rt * MROWS + t;
    if (i >= PRE) return;
    int d = i - j0;
    size_t word = ((size_t)(b*PRE + i))*NW + cb;
    if (d >= 63) { g_mask[word] = 0ull; return; }

    float4 bi = g_sboxes[b*PRE + i];
    float  ai = g_sarea [b*PRE + i];
    unsigned long long bits = iou_bits(bi, ai, cbox, carea, min(64, PRE - j0));
    if (d >= 0) bits &= (~0ull) << (d + 1);
    g_mask[word] = bits;
}

// ---------------- kernel 4b: full scan (fallback, per-batch early exit) ----------------
__global__ void nms_scan_kernel(float* __restrict__ out)
{
    int b    = blockIdx.x;
    if (g_done[b]) return;
    int lane = threadIdx.x;
    const unsigned FULL = 0xFFFFFFFFu;

    __shared__ unsigned long long removed[NW];
    __shared__ int keptList[POST];
    for (int w = lane; w < NW; w += 32) removed[w] = 0ull;
    __syncwarp();

    int kept = 0;
    for (int c = 0; c < NW && kept < POST; c++) {
        int r0 = c * 64;
        int ra = r0 + lane, rb2 = r0 + 32 + lane;

        bool va = (ra  < PRE) && ((g_keys_out[b*N_ANCH + ra ] & 0x3FFFFFFFu) != 0x3FFFFFFFu);
        bool vb = (rb2 < PRE) && ((g_keys_out[b*N_ANCH + rb2] & 0x3FFFFFFFu) != 0x3FFFFFFFu);
        unsigned lo = __ballot_sync(FULL, va);
        unsigned hi = __ballot_sync(FULL, vb);
        unsigned long long validm = (unsigned long long)lo | ((unsigned long long)hi << 32);

        unsigned long long m0 = (ra  < PRE) ? g_mask[((size_t)(b*PRE + ra ))*NW + c] : 0ull;
        unsigned long long m1 = (rb2 < PRE) ? g_mask[((size_t)(b*PRE + rb2))*NW + c] : 0ull;

        unsigned long long cand = validm & ~removed[c];
        unsigned long long keptbits = 0ull;
        while (cand && kept < POST) {
            int l = __ffsll((long long)cand) - 1;
            keptList[kept] = r0 + l;
            kept++;
            keptbits |= (1ull << l);
            unsigned long long intra = (l < 32) ? __shfl_sync(FULL, m0, l)
                                                : __shfl_sync(FULL, m1, l - 32);
            cand &= ~intra;
            cand &= ~(1ull << l);
        }

        if (keptbits) {
            unsigned long long acc0 = 0, acc1 = 0, acc2 = 0;
            int w0 = lane, w1 = lane + 32, w2 = lane + 64;
            unsigned long long kb2 = keptbits;
            while (kb2) {
                int l = __ffsll((long long)kb2) - 1;
                kb2 &= kb2 - 1;
                const unsigned long long* row = &g_mask[((size_t)(b*PRE + r0 + l))*NW];
                acc0 |= row[w0];
                if (w1 < NW) acc1 |= row[w1];
                if (w2 < NW) acc2 |= row[w2];
            }
            removed[w0] |= acc0;
            if (w1 < NW) removed[w1] |= acc1;
            if (w2 < NW) removed[w2] |= acc2;
        }
        __syncwarp();
    }

    for (int r = lane; r < POST; r += 32) {
        float* o = out + ((size_t)(b*POST + r))*5;
        if (r < kept) {
            float4 bx = g_sboxes[b*PRE + keptList[r]];
            o[0] = (float)b; o[1] = bx.x; o[2] = bx.y; o[3] = bx.z; o[4] = bx.w;
        } else {
            o[0] = (float)b; o[1] = 0.0f; o[2] = 0.0f; o[3] = 0.0f; o[4] = 0.0f;
        }
    }
}

// ---------------- launch ----------------
extern "C" void kernel_launch(void* const* d_in, const int* in_sizes, int n_in,
                              void* d_out, int out_size)
{
    const float* scores  = (const float*)d_in[0];
    const float* deltas  = (const float*)d_in[1];
    const float* anchors = (const float*)d_in[2];
    const float* iminfo  = (const float*)d_in[3];
    float* out = (float*)d_out;

    void *keys, *keysOut, *vals, *valsOut, *temp;
    cudaGetSymbolAddress(&keys,    g_keys);
    cudaGetSymbolAddress(&keysOut, g_keys_out);
    cudaGetSymbolAddress(&vals,    g_vals);
    cudaGetSymbolAddress(&valsOut, g_vals_out);
    cudaGetSymbolAddress(&temp,    g_temp);

    const int total = B_ * N_ANCH;
    prep_kernel<<<(total + 255) / 256, 256>>>(scores, deltas, anchors, iminfo);

    size_t temp_bytes = 0;
    cub::DeviceRadixSort::SortPairs(nullptr, temp_bytes,
        (const unsigned int*)keys, (unsigned int*)keysOut,
        (const int*)vals, (int*)valsOut, total, 0, 32);
    if (temp_bytes <= sizeof(g_temp)) {
        cub::DeviceRadixSort::SortPairs(temp, temp_bytes,
            (const unsigned int*)keys, (unsigned int*)keysOut,
            (const int*)vals, (int*)valsOut, total, 0, 32, (cudaStream_t)0);
    }

    gather_kernel<<<(B_*PRE + 255) / 256, 256>>>();

    // phase 1: corner mask + scan (handles ~all real inputs)
    dim3 m1grid(CH1, RT1, B_);
    mask1_kernel<<<m1grid, MROWS>>>();
    scan1_kernel<<<B_, 32>>>(out);

    // phase 2: full fallback, early-exits per batch when done
    dim3 mgrid(NW, MRT, B_);
    nms_mask_kernel<<<mgrid, MROWS>>>();
    nms_scan_kernel<<<B_, 32>>>(out);
}

// round 7
// speedup vs baseline: 1.9949x; 1.0913x over previous
#include <cuda_runtime.h>
#include <cuda_bf16.h>
#include <cub/cub.cuh>
#include <cstdint>

// ---------------- problem constants ----------------
#define FH_   50
#define FW_   84
#define A_    12
#define B_    4
#define PIX   (FH_*FW_)        // 4200
#define N_ANCH (PIX*A_)        // 50400
#define PRE   6000
#define POST  300
#define NMS_THR 0.7f
#define NBUCK 4096
#define NBLK  197              // ceil(N_ANCH/256)
#define CAPA  4096             // fast-path compact capacity (top-2048 select)
#define FCAP  8192             // fallback compact capacity (top-6000 select)
#define INV30 0x3FFFFFFFu
// fast-path corner: top R1 rows x R1 cols
#define R1    2048
#define CH1   32               // R1/64 column words
#define RT1   8                // R1/256 row tiles
#define MROWS 256

static_assert(CH1*64 == R1 && RT1*MROWS == R1, "phase1 dims");
static_assert(NBLK*256 >= N_ANCH, "NBLK");

// Correctly-rounded float exp: short fp64 poly + Ziv check, rare libdevice
// fallback. Bit-identical to (float)exp((double)x) for every input.
__device__ __forceinline__ float exp_cr(float x) {
    double xd = (double)x;
    double t  = xd * 1.4426950408889634;
    int    k  = __double2int_rn(t);
    double kd = (double)k;
    double r  = __fma_rn(kd, -0.6931471805599453,    xd);
    r         = __fma_rn(kd, -2.3190468138462996e-17, r);
    double p = 2.505210838544172e-08;
    p = __fma_rn(p, r, 2.755731922398589e-07);
    p = __fma_rn(p, r, 2.7557319223985893e-06);
    p = __fma_rn(p, r, 2.48015873015873e-05);
    p = __fma_rn(p, r, 1.984126984126984e-04);
    p = __fma_rn(p, r, 1.3888888888888889e-03);
    p = __fma_rn(p, r, 8.333333333333333e-03);
    p = __fma_rn(p, r, 4.1666666666666664e-02);
    p = __fma_rn(p, r, 0.16666666666666666);
    p = __fma_rn(p, r, 0.5);
    p = __fma_rn(p, r, 1.0);
    p = __fma_rn(p, r, 1.0);
    double yd = p * __longlong_as_double((long long)(1023 + k) << 52);
    float flo = (float)(yd * (1.0 - 1.0e-12));
    float fhi = (float)(yd * (1.0 + 1.0e-12));
    if (flo == fhi) return flo;
    return (float)exp(xd);
}

// ---------------- static device scratch ----------------
__device__ float4             g_boxes[B_*N_ANCH];
__device__ unsigned int       g_code [B_*N_ANCH];
__device__ int                g_hist [B_*NBUCK];
__device__ int                g_cutA [B_];
__device__ int                g_cutB [B_];
__device__ int                g_bcnt [B_*NBLK];
__device__ int                g_boff [B_*NBLK];
__device__ int                g_ovf  [B_];
__device__ unsigned long long g_ckeys[B_*CAPA];
__device__ int                g_cidx [B_*CAPA];
__device__ float4             g_sboxes[B_*R1];
__device__ float              g_sarea [B_*R1];
__device__ unsigned char      g_svalid[B_*R1];
__device__ int                g_done  [B_];
// corner mask (zero-init; fully-lower words never written -> stay 0)
__device__ unsigned long long g_mask1[(size_t)B_*R1*CH1];
// fallback scratch (never used on fast path)
__device__ unsigned long long g_fkeys[B_*FCAP];
__device__ int                g_fidx [B_*FCAP];

// ---------------- kernel 1: softmax + decode + code + histogram ----------------
__global__ void prep_kernel(const float* __restrict__ scores,
                            const float* __restrict__ deltas,
                            const float* __restrict__ anchors,
                            const float* __restrict__ iminfo)
{
    int idx = blockIdx.x * blockDim.x + threadIdx.x;
    if (idx >= B_*N_ANCH) return;
    int pix = idx % PIX;
    int ba  = idx / PIX;
    int b   = ba / A_;
    int a   = ba % A_;

    // softmax over (2a,2a+1): max-shift makes one exp exactly 1.0; single
    // E=exp(-|s1-s0|) reproduces the reference bitwise.
    const float* sp = scores + ((size_t)(b*2*A_ + 2*a))*PIX + pix;
    float s0 = sp[0];
    float s1 = sp[PIX];
    float dneg = (s1 >= s0) ? __fsub_rn(s0, s1) : __fsub_rn(s1, s0);
    float E     = exp_cr(dneg);
    float denom = __fadd_rn(E, 1.0f);
    float p = (s1 >= s0) ? __fdiv_rn(1.0f, denom) : __fdiv_rn(E, denom);

    const float* dp = deltas + ((size_t)(b*4*A_ + 4*a))*PIX + pix;
    float d0 = dp[0], d1 = dp[PIX], d2 = dp[2*PIX], d3 = dp[3*PIX];

    int i = pix*A_ + a;
    float4 an = reinterpret_cast<const float4*>(anchors)[i];

    float w  = an.z - an.x + 1.0f;
    float h  = an.w - an.y + 1.0f;
    float cx = __fadd_rn(an.x, __fmul_rn(0.5f, w));
    float cy = __fadd_rn(an.y, __fmul_rn(0.5f, h));
    float pcx = __fadd_rn(__fmul_rn(d0, w), cx);
    float pcy = __fadd_rn(__fmul_rn(d1, h), cy);
    float pw  = __fmul_rn(exp_cr(d2), w);
    float ph  = __fmul_rn(exp_cr(d3), h);
    float hx  = __fmul_rn(0.5f, pw);
    float hy  = __fmul_rn(0.5f, ph);
    float x1  = __fsub_rn(pcx, hx);
    float y1  = __fsub_rn(pcy, hy);
    float x2  = __fadd_rn(pcx, hx);
    float y2  = __fadd_rn(pcy, hy);

    float imh = iminfo[b*4+0], imw = iminfo[b*4+1];
    float sh  = iminfo[b*4+2], sw  = iminfo[b*4+3];
    float mw  = imw - 1.0f, mh = imh - 1.0f;
    x1 = fminf(fmaxf(x1, 0.0f), mw);
    y1 = fminf(fmaxf(y1, 0.0f), mh);
    x2 = fminf(fmaxf(x2, 0.0f), mw);
    y2 = fminf(fmaxf(y2, 0.0f), mh);

    float ws = x2 - x1 + 1.0f;
    float hs = y2 - y1 + 1.0f;
    bool valid = (ws >= __fmul_rn(16.0f, sw)) && (hs >= __fmul_rn(16.0f, sh));

    // 30-bit descending-score code; invalid sinks to sentinel code
    unsigned int code = valid ? (0x3F800000u - __float_as_uint(p)) : INV30;

    int gi = b*N_ANCH + i;
    g_code [gi] = code;
    g_boxes[gi] = make_float4(x1, y1, x2, y2);
    atomicAdd(&g_hist[b*NBUCK + (code >> 18)], 1);
}

// ---------------- kernel 2: cutoff buckets at rank R1 and rank PRE ----------------
__global__ void cutoff_kernel()
{
    int b = blockIdx.x;
    int lane = threadIdx.x;                  // 32 threads
    const unsigned FULL = 0xFFFFFFFFu;
    int running = 0;
    int cutA = NBUCK - 1, cutB = NBUCK - 1;
    bool fA = false, fB = false;
    for (int it = 0; it < NBUCK/32; it++) {
        int v = g_hist[b*NBUCK + it*32 + lane];
        int s = v;
        #pragma unroll
        for (int d = 1; d < 32; d <<= 1) {
            int t = __shfl_up_sync(FULL, s, d);
            if (lane >= d) s += t;
        }
        int cum = running + s;
        if (!fA) {
            unsigned mm = __ballot_sync(FULL, cum >= R1);
            if (mm) { cutA = it*32 + __ffs(mm) - 1; fA = true; }
        }
        if (!fB) {
            unsigned mm = __ballot_sync(FULL, cum >= PRE);
            if (mm) { cutB = it*32 + __ffs(mm) - 1; fB = true; }
        }
        if (fA && fB) break;
        running += __shfl_sync(FULL, s, 31);
    }
    if (lane == 0) { g_cutA[b] = cutA; g_cutB[b] = cutB; }
}

// ---------------- kernel 3: per-block predicate counts ----------------
__global__ void count_kernel()
{
    int blk = blockIdx.x, b = blockIdx.y;
    int i = blk*256 + threadIdx.x;
    int cutA = g_cutA[b];
    bool pred = (i < N_ANCH) && ((int)(g_code[b*N_ANCH + i] >> 18) <= cutA);
    int cnt = __syncthreads_count(pred);
    if (threadIdx.x == 0) g_bcnt[b*NBLK + blk] = cnt;
}

// ---------------- kernel 4: scan block counts + sentinel fill + ovf ----------------
__global__ void bscan_kernel()
{
    int b = blockIdx.x;
    int tid = threadIdx.x;                  // 256 threads
    __shared__ int sc[256];
    int v = (tid < NBLK) ? g_bcnt[b*NBLK + tid] : 0;
    sc[tid] = v;
    __syncthreads();
    for (int off = 1; off < 256; off <<= 1) {
        int t2 = (tid >= off) ? sc[tid - off] : 0;
        __syncthreads();
        sc[tid] += t2;
        __syncthreads();
    }
    if (tid < NBLK) g_boff[b*NBLK + tid] = sc[tid] - v;   // exclusive
    if (tid == 255) g_ovf[b] = (sc[255] > CAPA) ? 1 : 0;
    // sentinel-fill compact buffer (scatter runs in a later kernel)
    for (int j = tid; j < CAPA; j += 256) g_ckeys[b*CAPA + j] = ~0ull;
}

// ---------------- kernel 5: stable scatter of selected items ----------------
__global__ void scatter_kernel()
{
    int blk = blockIdx.x, b = blockIdx.y;
    int tid = threadIdx.x;                  // 256 threads
    int wid = tid >> 5, lane = tid & 31;
    const unsigned FULL = 0xFFFFFFFFu;
    __shared__ int wcnt[8];

    int i = blk*256 + tid;
    unsigned code = (i < N_ANCH) ? g_code[b*N_ANCH + i] : INV30;
    int cutA = g_cutA[b];
    bool pred = (i < N_ANCH) && ((int)(code >> 18) <= cutA);
    unsigned mm = __ballot_sync(FULL, pred);
    int pre = __popc(mm & ((1u << lane) - 1u));
    if (lane == 0) wcnt[wid] = __popc(mm);
    __syncthreads();
    if (tid == 0) {
        int ex = 0;
        #pragma unroll
        for (int w = 0; w < 8; w++) { int t = wcnt[w]; wcnt[w] = ex; ex += t; }
    }
    __syncthreads();
    if (pred) {
        int pos = g_boff[b*NBLK + blk] + wcnt[wid] + pre;
        if (pos < CAPA) {
            // key: 30-bit code | 16-bit stable compact position (index order)
            g_ckeys[b*CAPA + pos] = ((unsigned long long)code << 16) | (unsigned)pos;
            g_cidx [b*CAPA + pos] = i;
        }
    }
}

// ---------------- kernel 6: one-CTA sort of 4096 keys + fused gather ----------------
__global__ void sort_kernel()
{
    int b = blockIdx.x;
    int tid = threadIdx.x;                  // 1024 threads
    typedef cub::BlockRadixSort<unsigned long long, 1024, 4> BRS;
    __shared__ typename BRS::TempStorage ts;

    unsigned long long keys[4];
    #pragma unroll
    for (int k = 0; k < 4; k++) keys[k] = g_ckeys[b*CAPA + tid*4 + k];
    BRS(ts).Sort(keys, 0, 46);              // 46-bit (code|pos): exact tie order

    #pragma unroll
    for (int k = 0; k < 4; k++) {
        int r = tid*4 + k;
        if (r >= R1) break;
        unsigned long long key = keys[k];
        unsigned pos  = (unsigned)(key & 0xFFFFu);
        unsigned code = (unsigned)((key >> 16) & 0x3FFFFFFFull);
        bool ok = (pos < CAPA);
        float4 bx = make_float4(0.f, 0.f, 0.f, 0.f);
        float  ar = 0.f;
        if (ok) {
            int idx = g_cidx[b*CAPA + pos];
            bx = g_boxes[b*N_ANCH + idx];
            ar = (bx.z - bx.x + 1.0f) * (bx.w - bx.y + 1.0f);
        }
        g_sboxes[b*R1 + r] = bx;
        g_sarea [b*R1 + r] = ar;
        g_svalid[b*R1 + r] = (ok && code != INV30) ? 1 : 0;
    }
}

// ---------------- shared IoU bit computation ----------------
__device__ __forceinline__ unsigned long long iou_bits(
    float4 bi, float ai, const float4* cbox, const float* carea, int jmax)
{
    unsigned long long bits = 0ull;
    #pragma unroll 8
    for (int k = 0; k < jmax; k++) {
        float4 bj = cbox[k];
        float xx1 = fmaxf(bi.x, bj.x);
        float yy1 = fmaxf(bi.y, bj.y);
        float xx2 = fminf(bi.z, bj.z);
        float yy2 = fminf(bi.w, bj.w);
        float iw = fmaxf(xx2 - xx1 + 1.0f, 0.0f);
        float ih = fmaxf(yy2 - yy1 + 1.0f, 0.0f);
        float inter = __fmul_rn(iw, ih);
        float sum   = __fadd_rn(ai, carea[k]);
        // exact prefilter: iou>0.7 requires inter>0.41*sum; 4*inter>=sum is a
        // safe necessary condition -> kept-bit set is bit-identical
        if (__fmul_rn(inter, 4.0f) >= sum) {
            float uni = __fsub_rn(sum, inter);
            float iou = __fdiv_rn(inter, uni);
            if (iou > NMS_THR) bits |= (1ull << k);
        }
    }
    return bits;
}

// ---------------- kernel 7: corner mask (top R1 x R1) ----------------
__global__ void mask1_kernel()
{
    int cb = blockIdx.x;                    // column word, < CH1
    int rt = blockIdx.y;                    // row 256-tile, < RT1
    int b  = blockIdx.z;
    int j0 = cb * 64;
    if (j0 + 63 < rt * MROWS) return;       // fully-lower tile: words stay 0

    __shared__ float4 cbox[64];
    __shared__ float  carea[64];
    int t = threadIdx.x;
    if (t < 64) {
        cbox[t]  = g_sboxes[b*R1 + j0 + t];
        carea[t] = g_sarea [b*R1 + j0 + t];
    }
    __syncthreads();

    int i = rt * MROWS + t;                 // < R1
    int d = i - j0;
    size_t word = ((size_t)(b*R1 + i))*CH1 + cb;
    if (d >= 63) { g_mask1[word] = 0ull; return; }

    unsigned long long bits = iou_bits(g_sboxes[b*R1 + i], g_sarea[b*R1 + i],
                                       cbox, carea, 64);
    if (d >= 0) bits &= (~0ull) << (d + 1);
    g_mask1[word] = bits;
}

// ---------------- kernel 8: corner scan; writes output + g_done ----------------
__global__ void scan1_kernel(float* __restrict__ out)
{
    int b    = blockIdx.x;
    int lane = threadIdx.x;        // 32 threads
    const unsigned FULL = 0xFFFFFFFFu;

    __shared__ unsigned long long removed[CH1];
    __shared__ int keptList[POST];
    if (lane < CH1) removed[lane] = 0ull;
    __syncwarp();

    int kept = 0;
    for (int c = 0; c < CH1 && kept < POST; c++) {
        int r0 = c * 64;
        int ra = r0 + lane, rb2 = r0 + 32 + lane;

        unsigned lo = __ballot_sync(FULL, g_svalid[b*R1 + ra ] != 0);
        unsigned hi = __ballot_sync(FULL, g_svalid[b*R1 + rb2] != 0);
        unsigned long long validm = (unsigned long long)lo | ((unsigned long long)hi << 32);

        unsigned long long m0 = g_mask1[((size_t)(b*R1 + ra ))*CH1 + c];
        unsigned long long m1 = g_mask1[((size_t)(b*R1 + rb2))*CH1 + c];

        unsigned long long cand = validm & ~removed[c];
        unsigned long long keptbits = 0ull;
        while (cand && kept < POST) {
            int l = __ffsll((long long)cand) - 1;
            keptList[kept] = r0 + l;
            kept++;
            keptbits |= (1ull << l);
            unsigned long long intra = (l < 32) ? __shfl_sync(FULL, m0, l)
                                                : __shfl_sync(FULL, m1, l - 32);
            cand &= ~intra;
            cand &= ~(1ull << l);
        }

        if (keptbits) {
            unsigned long long acc = 0ull;           // lane -> word (CH1==32)
            unsigned long long kb2 = keptbits;
            while (kb2) {
                int l = __ffsll((long long)kb2) - 1;
                kb2 &= kb2 - 1;
                acc |= g_mask1[((size_t)(b*R1 + r0 + l))*CH1 + lane];
            }
            removed[lane] |= acc;
        }
        __syncwarp();
    }

    bool done = (kept >= POST) && (g_ovf[b] == 0);
    if (lane == 0) g_done[b] = done ? 1 : 0;
    if (done) {
        for (int r = lane; r < POST; r += 32) {
            float* o = out + ((size_t)(b*POST + r))*5;
            float4 bx = g_sboxes[b*R1 + keptList[r]];
            o[0] = (float)b; o[1] = bx.x; o[2] = bx.y; o[3] = bx.z; o[4] = bx.w;
        }
    }
}

// ---------------- kernel 9: slow exact fallback (per-batch early exit) ----------------
__global__ void fallback_kernel(float* __restrict__ out)
{
    int b = blockIdx.x;
    if (g_done[b]) return;                  // fast path handled this batch
    int tid = threadIdx.x;                  // 1024 threads
    int wid = tid >> 5, lane = tid & 31;
    const unsigned FULL = 0xFFFFFFFFu;

    __shared__ int wcnt[32];
    __shared__ int sBase, sWas;
    if (tid == 0) sBase = 0;
    __syncthreads();

    // stable in-CTA compaction of items with bucket <= cutB (top-PRE superset)
    int cutB = g_cutB[b];
    for (int c0 = 0; c0 < N_ANCH; c0 += 1024) {
        int i = c0 + tid;
        unsigned code = (i < N_ANCH) ? g_code[b*N_ANCH + i] : 0xFFFFFFFFu;
        bool pred = (i < N_ANCH) && ((int)(code >> 18) <= cutB);
        unsigned mm = __ballot_sync(FULL, pred);
        int pre = __popc(mm & ((1u << lane) - 1u));
        if (lane == 0) wcnt[wid] = __popc(mm);
        __syncthreads();
        if (tid == 0) {
            int ex = 0;
            #pragma unroll
            for (int w = 0; w < 32; w++) { int t = wcnt[w]; wcnt[w] = ex; ex += t; }
            sWas = sBase; sBase += ex;
        }
        __syncthreads();
        if (pred) {
            int pos = sWas + wcnt[wid] + pre;
            if (pos < FCAP) {
                g_fkeys[b*FCAP + pos] = ((unsigned long long)code << 16) | (unsigned)pos;
                g_fidx [b*FCAP + pos] = i;
            }
        }
        __syncthreads();
    }
    int total = sBase;
    for (int j = tid; j < FCAP; j += 1024)
        if (j >= total) g_fkeys[b*FCAP + j] = ~0ull;
    __syncthreads();

    // bitonic sort of FCAP keys in gmem (single CTA; perf irrelevant here)
    unsigned long long* Ak = &g_fkeys[b*FCAP];
    for (int k = 2; k <= FCAP; k <<= 1) {
        for (int j = k >> 1; j > 0; j >>= 1) {
            for (int i = tid; i < FCAP; i += 1024) {
                int ixj = i ^ j;
                if (ixj > i) {
                    bool up = ((i & k) == 0);
                    unsigned long long a = Ak[i], c = Ak[ixj];
                    if ((a > c) == up) { Ak[i] = c; Ak[ixj] = a; }
                }
            }
            __syncthreads();
        }
    }

    // greedy NMS over sorted top-PRE with exact IoU semantics
    __shared__ float4 kbox[POST];
    __shared__ float  karea[POST];
    __shared__ int kcnt, supp;
    if (tid == 0) kcnt = 0;
    __syncthreads();

    for (int r = 0; r < PRE; r++) {
        if (kcnt >= POST) break;            // consistent: read after sync
        unsigned long long key = Ak[r];
        unsigned pos  = (unsigned)(key & 0xFFFFu);
        unsigned code = (unsigned)((key >> 16) & 0x3FFFFFFFull);
        if (pos >= FCAP || code == INV30) break;  // sorted: rest invalid
        int idx = g_fidx[b*FCAP + pos];
        float4 bx = g_boxes[b*N_ANCH + idx];
        float ar = (bx.z - bx.x + 1.0f) * (bx.w - bx.y + 1.0f);
        if (tid == 0) supp = 0;
        __syncthreads();
        int kc = kcnt;
        for (int t = tid; t < kc; t += 1024) {
            float4 bj = kbox[t];
            float xx1 = fmaxf(bx.x, bj.x);
            float yy1 = fmaxf(bx.y, bj.y);
            float xx2 = fminf(bx.z, bj.z);
            float yy2 = fminf(bx.w, bj.w);
            float iw = fmaxf(xx2 - xx1 + 1.0f, 0.0f);
            float ih = fmaxf(yy2 - yy1 + 1.0f, 0.0f);
            float inter = __fmul_rn(iw, ih);
            float sum   = __fadd_rn(ar, karea[t]);
            if (__fmul_rn(inter, 4.0f) >= sum) {
                float uni = __fsub_rn(sum, inter);
                float iou = __fdiv_rn(inter, uni);
                if (iou > NMS_THR) supp = 1;
            }
        }
        __syncthreads();
        if (!supp && tid == 0) { kbox[kcnt] = bx; karea[kcnt] = ar; kcnt = kcnt + 1; }
        __syncthreads();
    }

    int kc = kcnt;
    for (int r = tid; r < POST; r += 1024) {
        float* o = out + ((size_t)(b*POST + r))*5;
        if (r < kc) {
            float4 bx = kbox[r];
            o[0] = (float)b; o[1] = bx.x; o[2] = bx.y; o[3] = bx.z; o[4] = bx.w;
        } else {
            o[0] = (float)b; o[1] = 0.0f; o[2] = 0.0f; o[3] = 0.0f; o[4] = 0.0f;
        }
    }
}

// ---------------- launch ----------------
extern "C" void kernel_launch(void* const* d_in, const int* in_sizes, int n_in,
                              void* d_out, int out_size)
{
    const float* scores  = (const float*)d_in[0];
    const float* deltas  = (const float*)d_in[1];
    const float* anchors = (const float*)d_in[2];
    const float* iminfo  = (const float*)d_in[3];
    float* out = (float*)d_out;

    void* hist;
    cudaGetSymbolAddress(&hist, g_hist);
    cudaMemsetAsync(hist, 0, B_*NBUCK*sizeof(int), 0);

    const int total = B_ * N_ANCH;
    prep_kernel<<<(total + 255) / 256, 256>>>(scores, deltas, anchors, iminfo);
    cutoff_kernel<<<B_, 32>>>();
    count_kernel<<<dim3(NBLK, B_), 256>>>();
    bscan_kernel<<<B_, 256>>>();
    scatter_kernel<<<dim3(NBLK, B_), 256>>>();
    sort_kernel<<<B_, 1024>>>();

    dim3 m1grid(CH1, RT1, B_);
    mask1_kernel<<<m1grid, MROWS>>>();
    scan1_kernel<<<B_, 32>>>(out);
    fallback_kernel<<<B_, 1024>>>(out);
}